// round 1
// baseline (speedup 1.0000x reference)
#include <cuda_runtime.h>
#include <math.h>

#define HH 1024
#define WW 1024
#define CC 128
#define EPSF 1e-8f

#define COLS_OUT 30           // output columns per block (lanes 1..30)
#define COLS_LOAD 32          // loaded columns incl. halo
#define ROWS_PB 64            // output rows per block
#define VSTRIDE 132           // floats per pixel vector in smem (padded: conflict-free LDS.128)
#define SLOT_FLOATS (COLS_LOAD * VSTRIDE)   // 4224
#define NSLOTS 4
#define NWARPS 8
#define SMEM_FLOATS (NSLOTS * SLOT_FLOATS + NWARPS * 32)

__global__ void __launch_bounds__(256)
cos_sim_box_kernel(const float* __restrict__ in, float* __restrict__ out)
{
    extern __shared__ float smem[];
    float* rowsbuf  = smem;                          // NSLOTS ring of normalized rows
    float* partials = smem + NSLOTS * SLOT_FLOATS;   // [8][32] warp partial dots

    const int tid  = threadIdx.x;
    const int warp = tid >> 5;
    const int lane = tid & 31;
    const int w0   = blockIdx.x * COLS_OUT;          // first output column of this strip
    const int r0   = blockIdx.y * ROWS_PB;

    // ---- load one image row (32 cols incl. halo), normalize, store to smem ring ----
    auto load_row = [&](int hr) {
        const int slot = (hr + 2 * NSLOTS) & (NSLOTS - 1);
        float* dst = rowsbuf + slot * SLOT_FLOATS;
        #pragma unroll
        for (int q = 0; q < 4; q++) {
            const int p  = warp * 4 + q;             // pixel within strip: 0..31
            const int gc = w0 + p - 1;               // global column (halo at p=0, p=31)
            float4 v = make_float4(0.f, 0.f, 0.f, 0.f);
            if (hr >= 0 && hr < HH && gc >= 0 && gc < WW) {
                const float4* g = reinterpret_cast<const float4*>(
                    in + ((size_t)hr * WW + gc) * CC);
                v = g[lane];                         // 512B contiguous per warp
            }
            float ss = v.x * v.x + v.y * v.y + v.z * v.z + v.w * v.w;
            #pragma unroll
            for (int o = 16; o > 0; o >>= 1)
                ss += __shfl_xor_sync(0xffffffffu, ss, o);
            const float nrm = sqrtf(ss);
            const float inv = 1.0f / fmaxf(nrm, EPSF);
            v.x *= inv; v.y *= inv; v.z *= inv; v.w *= inv;
            *reinterpret_cast<float4*>(dst + p * VSTRIDE + lane * 4) = v;
        }
    };

    load_row(r0 - 1);
    load_row(r0);

    for (int h = r0; h < r0 + ROWS_PB; h++) {
        load_row(h + 1);
        __syncthreads();   // ring slot (h+1) published; prior iter's reduce also done

        const float* rm = rowsbuf + (((h - 1) + 2 * NSLOTS) & (NSLOTS - 1)) * SLOT_FLOATS;
        const float* rc = rowsbuf + (((h    ) + 2 * NSLOTS) & (NSLOTS - 1)) * SLOT_FLOATS;
        const float* rp = rowsbuf + (((h + 1) + 2 * NSLOTS) & (NSLOTS - 1)) * SLOT_FLOATS;

        // lane = column within strip; warp owns 16 channels (4 float4 chunks)
        float acc = 0.f;
        const int base = lane * VSTRIDE + warp * 16;
        #pragma unroll
        for (int t = 0; t < 4; t++) {
            const float4 a = *reinterpret_cast<const float4*>(rm + base + t * 4);
            const float4 b = *reinterpret_cast<const float4*>(rc + base + t * 4);
            const float4 c = *reinterpret_cast<const float4*>(rp + base + t * 4);
            float4 v;                                  // vertical 3-sum
            v.x = a.x + b.x + c.x;
            v.y = a.y + b.y + c.y;
            v.z = a.z + b.z + c.z;
            v.w = a.w + b.w + c.w;
            float4 vl, vr;                             // horizontal neighbors via shuffle
            vl.x = __shfl_up_sync(0xffffffffu, v.x, 1);
            vl.y = __shfl_up_sync(0xffffffffu, v.y, 1);
            vl.z = __shfl_up_sync(0xffffffffu, v.z, 1);
            vl.w = __shfl_up_sync(0xffffffffu, v.w, 1);
            vr.x = __shfl_down_sync(0xffffffffu, v.x, 1);
            vr.y = __shfl_down_sync(0xffffffffu, v.y, 1);
            vr.z = __shfl_down_sync(0xffffffffu, v.z, 1);
            vr.w = __shfl_down_sync(0xffffffffu, v.w, 1);
            const float sx = v.x + vl.x + vr.x;        // S = 3x3 box sum of xn
            const float sy = v.y + vl.y + vr.y;
            const float sz = v.z + vl.z + vr.z;
            const float sw = v.w + vl.w + vr.w;
            acc += b.x * sx + b.y * sy + b.z * sz + b.w * sw;  // xn · S (16-ch partial)
        }
        partials[warp * 32 + lane] = acc;
        __syncthreads();

        if (tid < 32) {
            const int wl = tid;
            if (wl >= 1 && wl <= COLS_OUT) {
                const int gc = w0 + wl - 1;
                if (gc < WW) {
                    float s = 0.f;
                    #pragma unroll
                    for (int j = 0; j < NWARPS; j++) s += partials[j * 32 + wl];
                    out[(size_t)h * WW + gc] = s - 1.0f;
                }
            }
        }
        // next iter's first __syncthreads orders the reduce above against
        // the next partials write and the ring-slot reuse.
    }
}

extern "C" void kernel_launch(void* const* d_in, const int* in_sizes, int n_in,
                              void* d_out, int out_size)
{
    const float* in = (const float*)d_in[0];
    float* out = (float*)d_out;

    const size_t smem_bytes = SMEM_FLOATS * sizeof(float);   // ~68.6 KB
    cudaFuncSetAttribute(cos_sim_box_kernel,
                         cudaFuncAttributeMaxDynamicSharedMemorySize,
                         (int)smem_bytes);

    dim3 grid((WW + COLS_OUT - 1) / COLS_OUT, HH / ROWS_PB);  // 35 x 16
    dim3 block(256);
    cos_sim_box_kernel<<<grid, block, smem_bytes>>>(in, out);
}